// round 1
// baseline (speedup 1.0000x reference)
#include <cuda_runtime.h>

#define NB    128
#define PTS   2048
#define CIN   256
#define CMID  256
#define KPAD  264
#define BSTRIDE 132
#define ASTRIDE 36

// scratch (device globals — no allocations allowed)
__device__ float g_center[NB * 3];
__device__ float g_agg[NB * CMID];

__device__ __forceinline__ unsigned f2tf(float x) {
    unsigned r;
    asm("cvt.rna.tf32.f32 %0, %1;" : "=r"(r) : "f"(x));
    return r;
}

// ---------------- Kernel A: per-scene centroid ----------------
__global__ void centroid_kernel(const float* __restrict__ pos) {
    __shared__ float sh[3][256];
    const int b = blockIdx.x, t = threadIdx.x;
    const float* p = pos + (size_t)b * PTS * 3;
    float sx = 0.f, sy = 0.f, sz = 0.f;
    for (int i = t; i < PTS; i += 256) {
        sx += p[i * 3 + 0];
        sy += p[i * 3 + 1];
        sz += p[i * 3 + 2];
    }
    sh[0][t] = sx; sh[1][t] = sy; sh[2][t] = sz;
    __syncthreads();
    for (int s = 128; s > 0; s >>= 1) {
        if (t < s) {
            sh[0][t] += sh[0][t + s];
            sh[1][t] += sh[1][t + s];
            sh[2][t] += sh[2][t + s];
        }
        __syncthreads();
    }
    if (t < 3) g_center[b * 3 + t] = sh[t][0] * (1.0f / PTS);
}

// ---------------- Kernel B: fused GEMM1 + relu + segment-max ----------------
// grid: (128 scenes, 2 col-tiles); 256 threads; CTA tile 128(M) x 128(N), K=264 padded.
// K rows 0..255 = feature @ W1[0:256], rows 256..258 = rel-pos @ W1[256:259], 259..263 = 0.
__global__ __launch_bounds__(256, 1) void pointconv_kernel(
    const float* __restrict__ pos, const float* __restrict__ feature,
    const float* __restrict__ W1, const float* __restrict__ b1)
{
    extern __shared__ unsigned smem[];
    unsigned* Bs = smem;                          // KPAD * BSTRIDE (tf32 bits)
    unsigned* As = Bs + KPAD * BSTRIDE;           // 128 * ASTRIDE
    float* b1s   = (float*)(As + 128 * ASTRIDE);  // 128
    float* red   = b1s + 128;                     // 4 * 128

    const int tid  = threadIdx.x;
    const int lane = tid & 31, warp = tid >> 5;
    const int wm = warp & 3, wn = warp >> 2;      // 4 warps in M, 2 in N
    const int scene = blockIdx.x;
    const int colbase = blockIdx.y * 128;
    const int g = lane >> 2, tg = lane & 3;

    // ---- stage W1 tile (persistent, once per CTA) ----
    for (int i = tid; i < KPAD * 32; i += 256) {
        int k = i >> 5, nv = (i & 31) << 2;
        uint4 u = make_uint4(0u, 0u, 0u, 0u);
        if (k < CIN + 3) {
            const float4 f = *(const float4*)(W1 + (size_t)k * CMID + colbase + nv);
            u.x = f2tf(f.x); u.y = f2tf(f.y); u.z = f2tf(f.z); u.w = f2tf(f.w);
        }
        *(uint4*)(Bs + k * BSTRIDE + nv) = u;
    }
    if (tid < 128) b1s[tid] = b1[colbase + tid];
    __syncthreads();

    // bias values for the columns this thread owns
    float b1v[8][2];
#pragma unroll
    for (int ni = 0; ni < 8; ni++)
#pragma unroll
        for (int p = 0; p < 2; p++)
            b1v[ni][p] = b1s[wn * 64 + ni * 8 + tg * 2 + p];

    const float cx = g_center[scene * 3 + 0];
    const float cy = g_center[scene * 3 + 1];
    const float cz = g_center[scene * 3 + 2];

    float rmax[2][8][4];
#pragma unroll
    for (int mi = 0; mi < 2; mi++)
#pragma unroll
        for (int ni = 0; ni < 8; ni++)
#pragma unroll
            for (int j = 0; j < 4; j++) rmax[mi][ni][j] = 0.f;

    for (int ms = 0; ms < PTS / 128; ++ms) {
        const int rowbase = scene * PTS + ms * 128;
        float c[2][8][4];
#pragma unroll
        for (int mi = 0; mi < 2; mi++)
#pragma unroll
            for (int ni = 0; ni < 8; ni++)
#pragma unroll
                for (int j = 0; j < 4; j++) c[mi][ni][j] = 0.f;

        for (int ks = 0; ks < 9; ++ks) {
            __syncthreads();   // previous slice fully consumed
            if (ks < 8) {
                // feature slice: 128 rows x 32 k
                for (int i = tid; i < 128 * 8; i += 256) {
                    int row = i >> 3, v = (i & 7) << 2;
                    const float4 f = *(const float4*)(
                        feature + (size_t)(rowbase + row) * CIN + ks * 32 + v);
                    uint4 u;
                    u.x = f2tf(f.x); u.y = f2tf(f.y); u.z = f2tf(f.z); u.w = f2tf(f.w);
                    *(uint4*)(As + row * ASTRIDE + v) = u;
                }
            } else {
                // tail slice: rel-pos in k=0..2, zeros k=3..7
                for (int row = tid; row < 128; row += 256) {
                    int gr = rowbase + row;
                    float rx = pos[gr * 3 + 0] - cx;
                    float ry = pos[gr * 3 + 1] - cy;
                    float rz = pos[gr * 3 + 2] - cz;
                    *(uint4*)(As + row * ASTRIDE)     = make_uint4(f2tf(rx), f2tf(ry), f2tf(rz), 0u);
                    *(uint4*)(As + row * ASTRIDE + 4) = make_uint4(0u, 0u, 0u, 0u);
                }
            }
            __syncthreads();

            const int nkk = (ks == 8) ? 1 : 4;
            for (int kk = 0; kk < nkk; ++kk) {
                unsigned a[2][4];
#pragma unroll
                for (int mi = 0; mi < 2; mi++) {
                    int r  = wm * 32 + mi * 16 + g;
                    int kb = kk * 8 + tg;
                    a[mi][0] = As[r * ASTRIDE + kb];
                    a[mi][1] = As[(r + 8) * ASTRIDE + kb];
                    a[mi][2] = As[r * ASTRIDE + kb + 4];
                    a[mi][3] = As[(r + 8) * ASTRIDE + kb + 4];
                }
                const int kg = ks * 32 + kk * 8 + tg;
#pragma unroll
                for (int ni = 0; ni < 8; ni++) {
                    int n = wn * 64 + ni * 8 + g;
                    unsigned bb0 = Bs[kg * BSTRIDE + n];
                    unsigned bb1 = Bs[(kg + 4) * BSTRIDE + n];
#pragma unroll
                    for (int mi = 0; mi < 2; mi++) {
                        asm volatile(
                            "mma.sync.aligned.m16n8k8.row.col.f32.tf32.tf32.f32 "
                            "{%0,%1,%2,%3}, {%4,%5,%6,%7}, {%8,%9}, {%0,%1,%2,%3};\n"
                            : "+f"(c[mi][ni][0]), "+f"(c[mi][ni][1]),
                              "+f"(c[mi][ni][2]), "+f"(c[mi][ni][3])
                            : "r"(a[mi][0]), "r"(a[mi][1]), "r"(a[mi][2]), "r"(a[mi][3]),
                              "r"(bb0), "r"(bb1));
                    }
                }
            }
        }

        // epilogue: bias + relu + running segment max (registers only)
#pragma unroll
        for (int mi = 0; mi < 2; mi++)
#pragma unroll
            for (int ni = 0; ni < 8; ni++)
#pragma unroll
                for (int j = 0; j < 4; j++) {
                    float v = fmaxf(c[mi][ni][j] + b1v[ni][j & 1], 0.f);
                    rmax[mi][ni][j] = fmaxf(rmax[mi][ni][j], v);
                }
    }

    // ---- final column-max reduction ----
    float mm[8][2];
#pragma unroll
    for (int ni = 0; ni < 8; ni++)
#pragma unroll
        for (int p = 0; p < 2; p++)
            mm[ni][p] = fmaxf(fmaxf(rmax[0][ni][p], rmax[0][ni][p + 2]),
                              fmaxf(rmax[1][ni][p], rmax[1][ni][p + 2]));

#pragma unroll
    for (int off = 4; off < 32; off <<= 1)
#pragma unroll
        for (int ni = 0; ni < 8; ni++)
#pragma unroll
            for (int p = 0; p < 2; p++)
                mm[ni][p] = fmaxf(mm[ni][p],
                                  __shfl_xor_sync(0xffffffffu, mm[ni][p], off));

    __syncthreads();
    if (lane < 4) {
#pragma unroll
        for (int ni = 0; ni < 8; ni++)
#pragma unroll
            for (int p = 0; p < 2; p++)
                red[wm * 128 + wn * 64 + ni * 8 + lane * 2 + p] = mm[ni][p];
    }
    __syncthreads();
    if (tid < 128) {
        float v = fmaxf(fmaxf(red[tid], red[128 + tid]),
                        fmaxf(red[256 + tid], red[384 + tid]));
        g_agg[scene * CMID + colbase + tid] = v;
    }
}

// ---------------- Kernel C: head GEMM + softplus + rsample ----------------
__global__ void head_kernel(const float* __restrict__ W2, const float* __restrict__ b2,
                            const float* __restrict__ noise, float* __restrict__ out) {
    const int b = blockIdx.x, t = threadIdx.x;
    __shared__ float ag[CMID];
    ag[t] = g_agg[b * CMID + t];
    __syncthreads();
    float mu = b2[t], sr = b2[256 + t];
#pragma unroll 4
    for (int k = 0; k < CMID; k++) {
        float a = ag[k];
        mu = fmaf(a, W2[k * 512 + t], mu);
        sr = fmaf(a, W2[k * 512 + 256 + t], sr);
    }
    // numerically stable softplus: max(x,0) + log1p(exp(-|x|))
    float sp = fmaxf(sr, 0.f) + log1pf(expf(-fabsf(sr)));
    out[b * 256 + t] = mu + (sp + 1e-4f) * noise[b * 256 + t];
}

extern "C" void kernel_launch(void* const* d_in, const int* in_sizes, int n_in,
                              void* d_out, int out_size) {
    const float* pos     = (const float*)d_in[0];
    const float* feature = (const float*)d_in[1];
    // d_in[2] = batch: structurally i >> 11, never read (int64/int32 ambiguity)
    const float* W1      = (const float*)d_in[3];
    const float* b1      = (const float*)d_in[4];
    const float* W2      = (const float*)d_in[5];
    const float* b2      = (const float*)d_in[6];
    const float* noise   = (const float*)d_in[7];
    float* out = (float*)d_out;

    const int smem_bytes = (KPAD * BSTRIDE + 128 * ASTRIDE + 128 + 512) * 4; // 160384
    cudaFuncSetAttribute(pointconv_kernel,
                         cudaFuncAttributeMaxDynamicSharedMemorySize, smem_bytes);

    centroid_kernel<<<NB, 256>>>(pos);
    pointconv_kernel<<<dim3(NB, 2), 256, smem_bytes>>>(pos, feature, W1, b1);
    head_kernel<<<NB, CMID>>>(W2, b2, noise, out);
}

// round 3
// speedup vs baseline: 2.1990x; 2.1990x over previous
#include <cuda_runtime.h>
#include <cstdint>
#include <cfloat>

#define NB    128
#define PTS   2048
#define CIN   256
#define CMID  256

// ---- smem float offsets ----
#define BS_F    0                 // 33 kb-blocks * 128 n * 8 k' = 33792 floats
#define AS_F    33792             // 3 stages * 6144 floats (stage: 4 kb * 128 row * 12)
#define TAIL_F  (AS_F + 3*6144)   // 1536 floats
#define CEN_F   (TAIL_F + 1536)   // 4 floats
#define SMEM_FLOATS (CEN_F + 4)
#define SMEM_BYTES  (SMEM_FLOATS * 4)   // 215072 B

#define ASTAGE 6144
#define PERM(k) ((((k) & 3) << 1) | ((k) >> 2))

__device__ float g_agg[NB * CMID];

__device__ __forceinline__ uint32_t smem_u32(const void* p) {
    uint32_t a;
    asm("{ .reg .u64 t; cvta.to.shared.u64 t, %1; cvt.u32.u64 %0, t; }" : "=r"(a) : "l"(p));
    return a;
}
#define CP16(dst, src) asm volatile("cp.async.cg.shared.global [%0], [%1], 16;" :: "r"(dst), "l"(src) : "memory")
#define CP_COMMIT()    asm volatile("cp.async.commit_group;" ::: "memory")
#define CP_WAIT0()     asm volatile("cp.async.wait_group 0;" ::: "memory")
#define CP_WAIT1()     asm volatile("cp.async.wait_group 1;" ::: "memory")

#define MMA(c, a, b0, b1)                                                       \
    asm volatile("mma.sync.aligned.m16n8k8.row.col.f32.tf32.tf32.f32 "          \
        "{%0,%1,%2,%3}, {%4,%5,%6,%7}, {%8,%9}, {%0,%1,%2,%3};\n"               \
        : "+f"((c)[0]), "+f"((c)[1]), "+f"((c)[2]), "+f"((c)[3])                \
        : "r"(__float_as_uint((a)[0])), "r"(__float_as_uint((a)[1])),           \
          "r"(__float_as_uint((a)[2])), "r"(__float_as_uint((a)[3])),           \
          "r"(__float_as_uint(b0)), "r"(__float_as_uint(b1)))

// ==================== fused: centroid + GEMM1(tf32 mma) + relu + seg-max ====================
__global__ __launch_bounds__(256, 1)
void pointconv_kernel(const float* __restrict__ pos, const float* __restrict__ feat,
                      const float* __restrict__ W1, const float* __restrict__ b1)
{
    extern __shared__ float sm[];
    float* Bs = sm + BS_F;
    float* As = sm + AS_F;
    float* Tl = sm + TAIL_F;

    const int tid  = threadIdx.x;
    const int lane = tid & 31, warp = tid >> 5;
    const int wm = warp & 3, wn = warp >> 2;       // 4 warps in M, 2 in N
    const int g  = lane >> 2, tg = lane & 3;
    const int scene = blockIdx.y;
    const int colbase = blockIdx.x * 128;

    // ---- prologue: centroid partials, zero tail + last B block ----
    {
        float sx = 0.f, sy = 0.f, sz = 0.f;
        const float* p = pos + (size_t)scene * PTS * 3;
        for (int i = tid; i < PTS; i += 256) {
            sx += p[i * 3 + 0]; sy += p[i * 3 + 1]; sz += p[i * 3 + 2];
        }
        float* cs = As;   // alias A-ring (unused yet)
        cs[tid] = sx; cs[256 + tid] = sy; cs[512 + tid] = sz;
        for (int i = tid; i < 1024; i += 256) Bs[32 * 1024 + i] = 0.f;
        for (int i = tid; i < 1536; i += 256) Tl[i] = 0.f;
        __syncthreads();

        // stage W1 (permuted-k layout), coalesced LDG
        for (int idx = tid; idx < 259 * 128; idx += 256) {
            int k = idx >> 7, n = idx & 127;
            Bs[(k >> 3) * 1024 + n * 8 + PERM(k & 7)] = W1[(size_t)k * CMID + colbase + n];
        }
        // centroid tree (cs region)
        for (int s = 128; s > 0; s >>= 1) {
            __syncthreads();
            if (tid < s) {
                cs[tid] += cs[tid + s];
                cs[256 + tid] += cs[256 + tid + s];
                cs[512 + tid] += cs[512 + tid + s];
            }
        }
        __syncthreads();
        if (tid == 0) {
            sm[CEN_F + 0] = cs[0]   * (1.f / PTS);
            sm[CEN_F + 1] = cs[256] * (1.f / PTS);
            sm[CEN_F + 2] = cs[512] * (1.f / PTS);
        }
        __syncthreads();
    }
    const float cx = sm[CEN_F + 0], cy = sm[CEN_F + 1], cz = sm[CEN_F + 2];

    const uint32_t sb_as = smem_u32(As);

    // cp.async issue of feature slice q (q = chunk*8 + s), 16 KB -> stage q%3
    auto issue = [&](int q) {
        const int st = q % 3, s = q & 7;
        const float* base = feat + ((size_t)scene * PTS + (size_t)(q >> 3) * 128) * CIN + s * 32;
        const uint32_t d0 = sb_as + st * (ASTAGE * 4);
#pragma unroll
        for (int j = 0; j < 4; j++) {
            int ch = tid + 256 * j;                 // 0..1023
            int row = ch >> 3, kb = (ch >> 1) & 3, c = ch & 1;
            CP16(d0 + (uint32_t)(kb * 6144 + row * 48 + c * 16),
                 base + (size_t)row * CIN + kb * 8 + c * 4);
        }
        CP_COMMIT();
    };

    float acc[2][8][4], rmax[2][8][4];
#pragma unroll
    for (int mi = 0; mi < 2; mi++)
#pragma unroll
        for (int ni = 0; ni < 8; ni++)
#pragma unroll
            for (int j = 0; j < 4; j++) rmax[mi][ni][j] = -FLT_MAX;

    issue(0); issue(1);
    int nxt = 2;

    for (int ms = 0; ms < 16; ms++) {
#pragma unroll
        for (int mi = 0; mi < 2; mi++)
#pragma unroll
            for (int ni = 0; ni < 8; ni++)
#pragma unroll
                for (int j = 0; j < 4; j++) acc[mi][ni][j] = 0.f;

        for (int s = 0; s < 8; s++) {
            const int q = ms * 8 + s;
            if (q == 127) { CP_WAIT0(); } else { CP_WAIT1(); }
            __syncthreads();
            if (nxt < 128) issue(nxt++);
            if (s == 0 && tid < 128) {
                const int gr = scene * PTS + ms * 128 + tid;
                Tl[tid * 12 + 0] = pos[gr * 3 + 0] - cx;
                Tl[tid * 12 + 1] = pos[gr * 3 + 1] - cy;
                Tl[tid * 12 + 2] = pos[gr * 3 + 2] - cz;
            }
            const float* A = As + (q % 3) * ASTAGE;
#pragma unroll
            for (int kb = 0; kb < 4; kb++) {
                float a[2][4];
#pragma unroll
                for (int mi = 0; mi < 2; mi++) {
                    const int r = wm * 32 + mi * 16 + g;
                    a[mi][0] = A[kb * 1536 + r * 12 + tg];
                    a[mi][1] = A[kb * 1536 + (r + 8) * 12 + tg];
                    a[mi][2] = A[kb * 1536 + r * 12 + tg + 4];
                    a[mi][3] = A[kb * 1536 + (r + 8) * 12 + tg + 4];
                }
                const float* Bk = Bs + (s * 4 + kb) * 1024;
#pragma unroll
                for (int ni = 0; ni < 8; ni++) {
                    const int n = wn * 64 + ni * 8 + g;
                    const float2 bb = *(const float2*)(Bk + n * 8 + 2 * tg);
                    MMA(acc[0][ni], a[0], bb.x, bb.y);
                    MMA(acc[1][ni], a[1], bb.x, bb.y);
                }
            }
        }
        // tail k-step: rel-pos (k 256..263, zeros padded) — ordered by per-slice syncs
        {
            float a[2][4];
#pragma unroll
            for (int mi = 0; mi < 2; mi++) {
                const int r = wm * 32 + mi * 16 + g;
                a[mi][0] = Tl[r * 12 + tg];
                a[mi][1] = Tl[(r + 8) * 12 + tg];
                a[mi][2] = Tl[r * 12 + tg + 4];
                a[mi][3] = Tl[(r + 8) * 12 + tg + 4];
            }
            const float* Bk = Bs + 32 * 1024;
#pragma unroll
            for (int ni = 0; ni < 8; ni++) {
                const int n = wn * 64 + ni * 8 + g;
                const float2 bb = *(const float2*)(Bk + n * 8 + 2 * tg);
                MMA(acc[0][ni], a[0], bb.x, bb.y);
                MMA(acc[1][ni], a[1], bb.x, bb.y);
            }
        }
        // fold into running max (bias/relu deferred)
#pragma unroll
        for (int mi = 0; mi < 2; mi++)
#pragma unroll
            for (int ni = 0; ni < 8; ni++)
#pragma unroll
                for (int j = 0; j < 4; j++)
                    rmax[mi][ni][j] = fmaxf(rmax[mi][ni][j], acc[mi][ni][j]);
    }

    // ---- reduction over rows: frag -> lanes -> warps ----
    float mm[8][2];
#pragma unroll
    for (int ni = 0; ni < 8; ni++)
#pragma unroll
        for (int p = 0; p < 2; p++)
            mm[ni][p] = fmaxf(fmaxf(rmax[0][ni][p], rmax[0][ni][p + 2]),
                              fmaxf(rmax[1][ni][p], rmax[1][ni][p + 2]));
#pragma unroll
    for (int off = 4; off < 32; off <<= 1)
#pragma unroll
        for (int ni = 0; ni < 8; ni++)
#pragma unroll
            for (int p = 0; p < 2; p++)
                mm[ni][p] = fmaxf(mm[ni][p], __shfl_xor_sync(0xffffffffu, mm[ni][p], off));

    __syncthreads();               // all cp.async drained (wait0 at q=127) — safe to reuse As
    float* red = As;               // 4 wm copies * 128 cols
    if (lane < 4) {
#pragma unroll
        for (int ni = 0; ni < 8; ni++)
#pragma unroll
            for (int p = 0; p < 2; p++)
                red[wm * 128 + wn * 64 + ni * 8 + lane * 2 + p] = mm[ni][p];
    }
    __syncthreads();
    if (tid < 128) {
        float v = fmaxf(fmaxf(red[tid], red[128 + tid]),
                        fmaxf(red[256 + tid], red[384 + tid]));
        v = fmaxf(v + b1[colbase + tid], 0.f);
        g_agg[scene * CMID + colbase + tid] = v;
    }
}

// ==================== head: GEMM2 + softplus + rsample ====================
__global__ void head_kernel(const float* __restrict__ W2, const float* __restrict__ b2,
                            const float* __restrict__ noise, float* __restrict__ out) {
    const int b = blockIdx.x, t = threadIdx.x;
    __shared__ float ag[CMID];
    ag[t] = g_agg[b * CMID + t];
    __syncthreads();
    float mu = b2[t], sr = b2[256 + t];
#pragma unroll 4
    for (int k = 0; k < CMID; k++) {
        float a = ag[k];
        mu = fmaf(a, W2[k * 512 + t], mu);
        sr = fmaf(a, W2[k * 512 + 256 + t], sr);
    }
    float sp = fmaxf(sr, 0.f) + log1pf(expf(-fabsf(sr)));
    out[b * 256 + t] = mu + (sp + 1e-4f) * noise[b * 256 + t];
}

extern "C" void kernel_launch(void* const* d_in, const int* in_sizes, int n_in,
                              void* d_out, int out_size) {
    const float* pos     = (const float*)d_in[0];
    const float* feature = (const float*)d_in[1];
    // d_in[2] = batch: structurally i >> 11, never read
    const float* W1      = (const float*)d_in[3];
    const float* b1      = (const float*)d_in[4];
    const float* W2      = (const float*)d_in[5];
    const float* b2      = (const float*)d_in[6];
    const float* noise   = (const float*)d_in[7];
    float* out = (float*)d_out;

    cudaFuncSetAttribute(pointconv_kernel,
                         cudaFuncAttributeMaxDynamicSharedMemorySize, SMEM_BYTES);

    pointconv_kernel<<<dim3(2, NB), 256, SMEM_BYTES>>>(pos, feature, W1, b1);
    head_kernel<<<NB, CMID>>>(W2, b2, noise, out);
}

// round 4
// speedup vs baseline: 2.2616x; 1.0285x over previous
#include <cuda_runtime.h>
#include <cstdint>
#include <cfloat>

#define NB    128
#define PTS   2048
#define CIN   256
#define CMID  256

// ---- smem float offsets ----
#define BS_F    0                 // 33 kb-blocks * 128 n * 8 k' = 33792 floats
#define AS_F    33792             // 3 stages * 6144 floats (stage: 4 kb * 128 row * 12)
#define TAIL_F  (AS_F + 3*6144)   // 1536 floats
#define CEN_F   (TAIL_F + 1536)   // 4 floats
#define SMEM_FLOATS (CEN_F + 4)
#define SMEM_BYTES  (SMEM_FLOATS * 4)   // 215072 B

#define ASTAGE 6144
#define PERM(k) ((((k) & 3) << 1) | ((k) >> 2))

__device__ float g_agg[NB * CMID];

__device__ __forceinline__ uint32_t smem_u32(const void* p) {
    uint32_t a;
    asm("{ .reg .u64 t; cvta.to.shared.u64 t, %1; cvt.u32.u64 %0, t; }" : "=r"(a) : "l"(p));
    return a;
}
#define CP16(dst, src) asm volatile("cp.async.cg.shared.global [%0], [%1], 16;" :: "r"(dst), "l"(src) : "memory")
#define CP_COMMIT()    asm volatile("cp.async.commit_group;" ::: "memory")
#define CP_WAIT0()     asm volatile("cp.async.wait_group 0;" ::: "memory")
#define CP_WAIT1()     asm volatile("cp.async.wait_group 1;" ::: "memory")

#define MMA(c, a, b0, b1)                                                       \
    asm volatile("mma.sync.aligned.m16n8k8.row.col.f32.tf32.tf32.f32 "          \
        "{%0,%1,%2,%3}, {%4,%5,%6,%7}, {%8,%9}, {%0,%1,%2,%3};\n"               \
        : "+f"((c)[0]), "+f"((c)[1]), "+f"((c)[2]), "+f"((c)[3])                \
        : "r"(__float_as_uint((a)[0])), "r"(__float_as_uint((a)[1])),           \
          "r"(__float_as_uint((a)[2])), "r"(__float_as_uint((a)[3])),           \
          "r"(__float_as_uint(b0)), "r"(__float_as_uint(b1)))

// ==================== fused: centroid + GEMM1(tf32 mma) + relu + seg-max ====================
// 512 threads = 16 warps: 8 warps in M (16 rows each), 2 in N (64 cols each).
__global__ __launch_bounds__(512, 1)
void pointconv_kernel(const float* __restrict__ pos, const float* __restrict__ feat,
                      const float* __restrict__ W1, const float* __restrict__ b1)
{
    extern __shared__ float sm[];
    float* Bs = sm + BS_F;
    float* As = sm + AS_F;
    float* Tl = sm + TAIL_F;

    const int tid  = threadIdx.x;
    const int lane = tid & 31, warp = tid >> 5;
    const int wm = warp & 7, wn = warp >> 3;       // 8 warps in M, 2 in N
    const int g  = lane >> 2, tg = lane & 3;
    const int scene = blockIdx.y;
    const int colbase = blockIdx.x * 128;

    // ---- prologue: centroid partials, zero tail + last B block, stage W1 ----
    {
        float sx = 0.f, sy = 0.f, sz = 0.f;
        const float* p = pos + (size_t)scene * PTS * 3;
        for (int i = tid; i < PTS; i += 512) {
            sx += p[i * 3 + 0]; sy += p[i * 3 + 1]; sz += p[i * 3 + 2];
        }
        float* cs = As;   // alias A-ring (unused yet): 3 x 512 floats
        cs[tid] = sx; cs[512 + tid] = sy; cs[1024 + tid] = sz;
        for (int i = tid; i < 1024; i += 512) Bs[32 * 1024 + i] = 0.f;
        for (int i = tid; i < 1536; i += 512) Tl[i] = 0.f;
        __syncthreads();

        // stage W1 (permuted-k layout), coalesced LDG
        for (int idx = tid; idx < 259 * 128; idx += 512) {
            int k = idx >> 7, n = idx & 127;
            Bs[(k >> 3) * 1024 + n * 8 + PERM(k & 7)] = W1[(size_t)k * CMID + colbase + n];
        }
        // centroid tree
        for (int s = 256; s > 0; s >>= 1) {
            __syncthreads();
            if (tid < s) {
                cs[tid] += cs[tid + s];
                cs[512 + tid] += cs[512 + tid + s];
                cs[1024 + tid] += cs[1024 + tid + s];
            }
        }
        __syncthreads();
        if (tid == 0) {
            sm[CEN_F + 0] = cs[0]    * (1.f / PTS);
            sm[CEN_F + 1] = cs[512]  * (1.f / PTS);
            sm[CEN_F + 2] = cs[1024] * (1.f / PTS);
        }
        __syncthreads();
    }
    const float cx = sm[CEN_F + 0], cy = sm[CEN_F + 1], cz = sm[CEN_F + 2];

    const uint32_t sb_as = smem_u32(As);

    // cp.async issue of feature slice q (q = chunk*8 + s), 16 KB -> stage q%3
    auto issue = [&](int q) {
        const int st = q % 3, s = q & 7;
        const float* base = feat + ((size_t)scene * PTS + (size_t)(q >> 3) * 128) * CIN + s * 32;
        const uint32_t d0 = sb_as + st * (ASTAGE * 4);
#pragma unroll
        for (int j = 0; j < 2; j++) {
            int ch = tid + 512 * j;                 // 0..1023
            int row = ch >> 3, kb = (ch >> 1) & 3, c = ch & 1;
            CP16(d0 + (uint32_t)(kb * 6144 + row * 48 + c * 16),
                 base + (size_t)row * CIN + kb * 8 + c * 4);
        }
        CP_COMMIT();
    };

    float acc[8][4], rmax[8][4];
#pragma unroll
    for (int ni = 0; ni < 8; ni++)
#pragma unroll
        for (int j = 0; j < 4; j++) rmax[ni][j] = -FLT_MAX;

    issue(0); issue(1);
    int nxt = 2;

    const int r = wm * 16 + g;                      // this warp's A rows: r, r+8

    for (int ms = 0; ms < 16; ms++) {
#pragma unroll
        for (int ni = 0; ni < 8; ni++)
#pragma unroll
            for (int j = 0; j < 4; j++) acc[ni][j] = 0.f;

        for (int s = 0; s < 8; s++) {
            const int q = ms * 8 + s;
            if (q == 127) { CP_WAIT0(); } else { CP_WAIT1(); }
            __syncthreads();
            if (nxt < 128) issue(nxt++);
            if (s == 0 && tid < 128) {
                const int gr = scene * PTS + ms * 128 + tid;
                Tl[tid * 12 + 0] = pos[gr * 3 + 0] - cx;
                Tl[tid * 12 + 1] = pos[gr * 3 + 1] - cy;
                Tl[tid * 12 + 2] = pos[gr * 3 + 2] - cz;
            }
            const float* A = As + (q % 3) * ASTAGE;
#pragma unroll
            for (int kb = 0; kb < 4; kb++) {
                float a[4];
                a[0] = A[kb * 1536 + r * 12 + tg];
                a[1] = A[kb * 1536 + (r + 8) * 12 + tg];
                a[2] = A[kb * 1536 + r * 12 + tg + 4];
                a[3] = A[kb * 1536 + (r + 8) * 12 + tg + 4];
                const float* Bk = Bs + (s * 4 + kb) * 1024;
#pragma unroll
                for (int ni = 0; ni < 8; ni++) {
                    const int n = wn * 64 + ni * 8 + g;
                    const float2 bb = *(const float2*)(Bk + n * 8 + 2 * tg);
                    MMA(acc[ni], a, bb.x, bb.y);
                }
            }
        }
        // tail k-step: rel-pos (k 256..263, zeros padded)
        {
            float a[4];
            a[0] = Tl[r * 12 + tg];
            a[1] = Tl[(r + 8) * 12 + tg];
            a[2] = Tl[r * 12 + tg + 4];
            a[3] = Tl[(r + 8) * 12 + tg + 4];
            const float* Bk = Bs + 32 * 1024;
#pragma unroll
            for (int ni = 0; ni < 8; ni++) {
                const int n = wn * 64 + ni * 8 + g;
                const float2 bb = *(const float2*)(Bk + n * 8 + 2 * tg);
                MMA(acc[ni], a, bb.x, bb.y);
            }
        }
        // fold into running max (bias/relu deferred)
#pragma unroll
        for (int ni = 0; ni < 8; ni++)
#pragma unroll
            for (int j = 0; j < 4; j++)
                rmax[ni][j] = fmaxf(rmax[ni][j], acc[ni][j]);
    }

    // ---- reduction over rows: frag -> lanes -> warps ----
    float mm[8][2];
#pragma unroll
    for (int ni = 0; ni < 8; ni++)
#pragma unroll
        for (int p = 0; p < 2; p++)
            mm[ni][p] = fmaxf(rmax[ni][p], rmax[ni][p + 2]);
#pragma unroll
    for (int off = 4; off < 32; off <<= 1)
#pragma unroll
        for (int ni = 0; ni < 8; ni++)
#pragma unroll
            for (int p = 0; p < 2; p++)
                mm[ni][p] = fmaxf(mm[ni][p], __shfl_xor_sync(0xffffffffu, mm[ni][p], off));

    __syncthreads();               // cp.async drained (wait0 at q=127) — safe to reuse As
    float* red = As;               // 8 wm copies * 128 cols = 1024 floats
    if (lane < 4) {
#pragma unroll
        for (int ni = 0; ni < 8; ni++)
#pragma unroll
            for (int p = 0; p < 2; p++)
                red[wm * 128 + wn * 64 + ni * 8 + lane * 2 + p] = mm[ni][p];
    }
    __syncthreads();
    if (tid < 128) {
        float v = red[tid];
#pragma unroll
        for (int w = 1; w < 8; w++) v = fmaxf(v, red[w * 128 + tid]);
        v = fmaxf(v + b1[colbase + tid], 0.f);
        g_agg[scene * CMID + colbase + tid] = v;
    }
}

// ==================== head: GEMM2 + softplus + rsample ====================
// 512 threads: t<256 -> mu col t, t>=256 -> sigma col t-256. Batched loads, 4 accs.
__global__ __launch_bounds__(512, 1)
void head_kernel(const float* __restrict__ W2, const float* __restrict__ b2,
                 const float* __restrict__ noise, float* __restrict__ out) {
    const int b = blockIdx.x, t = threadIdx.x;
    __shared__ float ag[CMID];
    __shared__ float sp_sh[CMID];
    if (t < CMID) ag[t] = g_agg[b * CMID + t];
    __syncthreads();

    float a0 = 0.f, a1 = 0.f, a2 = 0.f, a3 = 0.f;
    for (int k = 0; k < CMID; k += 16) {
        float w[16];
#pragma unroll
        for (int j = 0; j < 16; j++) w[j] = W2[(size_t)(k + j) * 512 + t];
#pragma unroll
        for (int j = 0; j < 16; j += 4) {
            a0 = fmaf(ag[k + j + 0], w[j + 0], a0);
            a1 = fmaf(ag[k + j + 1], w[j + 1], a1);
            a2 = fmaf(ag[k + j + 2], w[j + 2], a2);
            a3 = fmaf(ag[k + j + 3], w[j + 3], a3);
        }
    }
    float acc = (a0 + a1) + (a2 + a3) + b2[t];

    if (t >= 256) {
        float sp = fmaxf(acc, 0.f) + log1pf(expf(-fabsf(acc)));
        sp_sh[t - 256] = sp + 1e-4f;
    }
    __syncthreads();
    if (t < 256) {
        out[b * 256 + t] = acc + sp_sh[t] * noise[b * 256 + t];
    }
}

extern "C" void kernel_launch(void* const* d_in, const int* in_sizes, int n_in,
                              void* d_out, int out_size) {
    const float* pos     = (const float*)d_in[0];
    const float* feature = (const float*)d_in[1];
    // d_in[2] = batch: structurally i >> 11, never read
    const float* W1      = (const float*)d_in[3];
    const float* b1      = (const float*)d_in[4];
    const float* W2      = (const float*)d_in[5];
    const float* b2      = (const float*)d_in[6];
    const float* noise   = (const float*)d_in[7];
    float* out = (float*)d_out;

    cudaFuncSetAttribute(pointconv_kernel,
                         cudaFuncAttributeMaxDynamicSharedMemorySize, SMEM_BYTES);

    pointconv_kernel<<<dim3(2, NB), 512, SMEM_BYTES>>>(pos, feature, W1, b1);
    head_kernel<<<NB, 512>>>(W2, b2, noise, out);
}

// round 5
// speedup vs baseline: 3.7457x; 1.6563x over previous
#include <cuda_runtime.h>
#include <cuda_fp16.h>
#include <cstdint>
#include <cfloat>

#define NB  128
#define PTS 2048
#define CIN 256

// ---- smem word (uint32) offsets ----
#define BH_W   0                      // W1 fp16: 17 k16-blocks * 256 n * 8 words
#define FB_W   34816                  // A fp16 operand, 2 bufs * 128 rows * 24 words
#define TL_W   40960                  // tail A fp16: 128 rows * 8 words
#define ST_W   41984                  // fp32 stage ring: 3 * 128 rows * 36 words
#define RED_W  55808                  // 1024 floats (also centroid scratch)
#define CEN_W  56832
#define SMEM_WORDS 56840
#define SMEM_BYTES (SMEM_WORDS * 4)   // 227360 B

__device__ float g_agg[NB * 256];

__device__ __forceinline__ uint32_t smem_u32(const void* p) {
    uint32_t a;
    asm("{ .reg .u64 t; cvta.to.shared.u64 t, %1; cvt.u32.u64 %0, t; }" : "=r"(a) : "l"(p));
    return a;
}
#define CP16(dst, src) asm volatile("cp.async.cg.shared.global [%0], [%1], 16;" :: "r"(dst), "l"(src) : "memory")
#define CPC()   asm volatile("cp.async.commit_group;" ::: "memory")
#define CPW(n)  asm volatile("cp.async.wait_group %0;" :: "n"(n) : "memory")

#define MMA16(c, a, b)                                                          \
    asm volatile("mma.sync.aligned.m16n8k16.row.col.f32.f16.f16.f32 "           \
        "{%0,%1,%2,%3}, {%4,%5,%6,%7}, {%8,%9}, {%0,%1,%2,%3};\n"               \
        : "+f"((c)[0]), "+f"((c)[1]), "+f"((c)[2]), "+f"((c)[3])                \
        : "r"((a)[0]), "r"((a)[1]), "r"((a)[2]), "r"((a)[3]),                   \
          "r"((b).x), "r"((b).y))

// ==================== fused: centroid + GEMM1(fp16 mma) + relu + seg-max ====================
// 1 CTA per scene. 512 threads = 16 warps: 4 M-warps x 4 N-warps; warp tile 32x64.
// K layout: 16 k16-blocks of feature + 1 tail block (rel-pos k256..258, zero pad).
// fp16 k-perm within a 16-block: pos(k) = ((k&7)>>1)*4 + ((k>>3)&1)*2 + (k&1)
// so (k, k+1, k+8, k+9) are 4 consecutive halves -> one LDS.64 per mma fragment pair.
__global__ __launch_bounds__(512, 1)
void pointconv_kernel(const float* __restrict__ pos, const float* __restrict__ feat,
                      const float* __restrict__ W1, const float* __restrict__ b1)
{
    extern __shared__ uint32_t smw[];
    const uint32_t sb = smem_u32(smw);

    const int tid  = threadIdx.x;
    const int lane = tid & 31, warp = tid >> 5;
    const int wm = warp & 3, wn = warp >> 2;      // 4 M-warps, 4 N-warps
    const int g  = lane >> 2, tg = lane & 3;
    const int scene = blockIdx.x;

    // cp.async issue of feature slice q (chunk q>>3, k-slice q&7) into stage q%3
    auto issue = [&](int q) {
        const int st = q % 3;
        const float* base = feat + ((size_t)scene * PTS + (size_t)(q >> 3) * 128) * CIN + (q & 7) * 32;
        const uint32_t d0 = sb + (ST_W + st * 4608) * 4;
#pragma unroll
        for (int j = 0; j < 2; j++) {
            int ch = tid + 512 * j;               // 0..1023 chunks of 16B
            int row = ch >> 3, c = ch & 7;
            CP16(d0 + (uint32_t)(row * 144 + c * 16), base + (size_t)row * CIN + c * 4);
        }
        CPC();
    };

    // fp32 stage -> fp16 perm operand buffer (one slice)
    auto convert = [&](int q) {
        const int st = q % 3, bf = q & 1;
        const int row = tid >> 2, seg = tid & 3;
        const float4* sp4 = (const float4*)(smw + ST_W + st * 4608 + row * 36 + seg * 8);
        float4 f0 = sp4[0], f1 = sp4[1];
        half2* dst = (half2*)(smw + FB_W + bf * 3072 + row * 24 + (seg >> 1) * 8 + (seg & 1));
        dst[0] = __floats2half2_rn(f0.x, f0.y);
        dst[2] = __floats2half2_rn(f0.z, f0.w);
        dst[4] = __floats2half2_rn(f1.x, f1.y);
        dst[6] = __floats2half2_rn(f1.z, f1.w);
    };

    // ---- prologue ----
    issue(0); issue(1); issue(2);

    // zero tail-A and tail-B block (rarely-written positions stay 0)
    for (int i = tid; i < 1024; i += 512) smw[TL_W + i] = 0;
    for (int i = tid; i < 2048; i += 512) smw[BH_W + 16 * 2048 + i] = 0;

    // centroid partials -> warp shuffle -> red
    {
        float sx = 0.f, sy = 0.f, sz = 0.f;
        const float* p = pos + (size_t)scene * PTS * 3;
        for (int i = tid; i < PTS; i += 512) {
            sx += p[i * 3 + 0]; sy += p[i * 3 + 1]; sz += p[i * 3 + 2];
        }
#pragma unroll
        for (int off = 16; off > 0; off >>= 1) {
            sx += __shfl_xor_sync(0xffffffffu, sx, off);
            sy += __shfl_xor_sync(0xffffffffu, sy, off);
            sz += __shfl_xor_sync(0xffffffffu, sz, off);
        }
        float* red = (float*)(smw + RED_W);
        if (lane == 0) { red[warp] = sx; red[32 + warp] = sy; red[64 + warp] = sz; }
    }
    __syncthreads();
    if (tid < 3) {
        const float* red = (const float*)(smw + RED_W);
        float s = 0.f;
        for (int w = 0; w < 16; w++) s += red[tid * 32 + w];
        ((float*)(smw + CEN_W))[tid] = s * (1.f / PTS);
    }
    // stage W1 -> fp16 perm layout (includes tail rows 256..258 into block 16)
    for (int idx = tid; idx < 259 * 256; idx += 512) {
        int k = idx >> 8, n = idx & 255;
        float v = W1[(size_t)k * 256 + n];
        int kb = k >> 4, kk = k & 15;
        int p_ = ((kk & 7) >> 1) * 4 + ((kk >> 3) & 1) * 2 + (kk & 1);
        ((__half*)(smw + BH_W))[kb * 4096 + n * 16 + p_] = __float2half(v);
    }
    CPW(2);
    __syncthreads();
    convert(0);

    const float cx = ((float*)(smw + CEN_W))[0];
    const float cy = ((float*)(smw + CEN_W))[1];
    const float cz = ((float*)(smw + CEN_W))[2];

    float acc[2][8][4], rmax[8][2];
#pragma unroll
    for (int ni = 0; ni < 8; ni++) { rmax[ni][0] = -FLT_MAX; rmax[ni][1] = -FLT_MAX; }

    // ---- main loop: 128 slices (16 chunks x 8) ----
    for (int i = 0; i < 128; i++) {
        CPW(1);
        __syncthreads();
        if (i + 3 < 128) issue(i + 3);
        if (i + 1 < 128) convert(i + 1);

        if ((i & 7) == 0) {
#pragma unroll
            for (int mi = 0; mi < 2; mi++)
#pragma unroll
                for (int ni = 0; ni < 8; ni++)
#pragma unroll
                    for (int j = 0; j < 4; j++) acc[mi][ni][j] = 0.f;
            if (tid < 128) {   // rel-pos for this chunk into tail buffer
                const int gr = scene * PTS + (i >> 3) * 128 + tid;
                ((half2*)(smw + TL_W + tid * 8))[0] =
                    __floats2half2_rn(pos[gr * 3 + 0] - cx, pos[gr * 3 + 1] - cy);
                ((half2*)(smw + TL_W + tid * 8 + 2))[0] =
                    __floats2half2_rn(pos[gr * 3 + 2] - cz, 0.f);
            }
        }

        // mma over this 32k slice (2 k16 steps)
        const uint32_t* fb = smw + FB_W + (i & 1) * 3072;
#pragma unroll
        for (int step = 0; step < 2; step++) {
            uint32_t a[2][4];
#pragma unroll
            for (int mi = 0; mi < 2; mi++) {
                const int R = wm * 32 + mi * 16 + g;
                uint2 x = *(const uint2*)(fb + R * 24 + step * 8 + 2 * tg);
                uint2 y = *(const uint2*)(fb + (R + 8) * 24 + step * 8 + 2 * tg);
                a[mi][0] = x.x; a[mi][1] = y.x; a[mi][2] = x.y; a[mi][3] = y.y;
            }
            const uint32_t* bh = smw + BH_W + ((i & 7) * 2 + step) * 2048;
#pragma unroll
            for (int ni = 0; ni < 8; ni++) {
                uint2 b = *(const uint2*)(bh + (wn * 64 + ni * 8 + g) * 8 + 2 * tg);
                MMA16(acc[0][ni], a[0], b);
                MMA16(acc[1][ni], a[1], b);
            }
        }

        if ((i & 7) == 7) {
            // tail k16 step: rel-pos
            uint32_t a[2][4];
#pragma unroll
            for (int mi = 0; mi < 2; mi++) {
                const int R = wm * 32 + mi * 16 + g;
                uint2 x = *(const uint2*)(smw + TL_W + R * 8 + 2 * tg);
                uint2 y = *(const uint2*)(smw + TL_W + (R + 8) * 8 + 2 * tg);
                a[mi][0] = x.x; a[mi][1] = y.x; a[mi][2] = x.y; a[mi][3] = y.y;
            }
            const uint32_t* bh = smw + BH_W + 16 * 2048;
#pragma unroll
            for (int ni = 0; ni < 8; ni++) {
                uint2 b = *(const uint2*)(bh + (wn * 64 + ni * 8 + g) * 8 + 2 * tg);
                MMA16(acc[0][ni], a[0], b);
                MMA16(acc[1][ni], a[1], b);
            }
            // fold into running max (bias/relu deferred: max commutes with +b, relu)
#pragma unroll
            for (int ni = 0; ni < 8; ni++)
#pragma unroll
                for (int p = 0; p < 2; p++)
                    rmax[ni][p] = fmaxf(rmax[ni][p],
                        fmaxf(fmaxf(acc[0][ni][p], acc[0][ni][p + 2]),
                              fmaxf(acc[1][ni][p], acc[1][ni][p + 2])));
        }
    }

    // ---- reduce rows: shuffle over g, combine 4 wm warps in smem ----
#pragma unroll
    for (int off = 4; off < 32; off <<= 1)
#pragma unroll
        for (int ni = 0; ni < 8; ni++)
#pragma unroll
            for (int p = 0; p < 2; p++)
                rmax[ni][p] = fmaxf(rmax[ni][p], __shfl_xor_sync(0xffffffffu, rmax[ni][p], off));

    __syncthreads();
    float* red = (float*)(smw + RED_W);
    if (lane < 4) {
#pragma unroll
        for (int ni = 0; ni < 8; ni++)
#pragma unroll
            for (int p = 0; p < 2; p++)
                red[wm * 256 + wn * 64 + ni * 8 + 2 * tg + p] = rmax[ni][p];
    }
    __syncthreads();
    if (tid < 256) {
        float v = fmaxf(fmaxf(red[tid], red[256 + tid]),
                        fmaxf(red[512 + tid], red[768 + tid]));
        v = fmaxf(v + b1[tid], 0.f);
        g_agg[scene * 256 + tid] = v;
    }
}

// ==================== head: GEMM2 + softplus + rsample ====================
// grid (2 col-blocks of 128, 16 scene-blocks of 8); each thread: 1 col x 4 scenes, mu+sigma.
__global__ __launch_bounds__(256, 1)
void head_kernel(const float* __restrict__ W2, const float* __restrict__ b2,
                 const float* __restrict__ noise, float* __restrict__ out) {
    const int t = threadIdx.x;
    const int col = blockIdx.x * 128 + (t & 127);
    const int sg  = (t >> 7) * 4;
    const int sbase = blockIdx.y * 8;
    __shared__ float ag[256 * 8];
#pragma unroll
    for (int i = 0; i < 8; i++) ag[t * 8 + i] = g_agg[(sbase + i) * 256 + t];
    __syncthreads();

    float amu[4] = {0.f, 0.f, 0.f, 0.f}, asg[4] = {0.f, 0.f, 0.f, 0.f};
#pragma unroll 4
    for (int k = 0; k < 256; k++) {
        const float wmu = W2[(size_t)k * 512 + col];
        const float wsg = W2[(size_t)k * 512 + col + 256];
        const float4 av = *(const float4*)&ag[k * 8 + sg];
        amu[0] = fmaf(av.x, wmu, amu[0]); asg[0] = fmaf(av.x, wsg, asg[0]);
        amu[1] = fmaf(av.y, wmu, amu[1]); asg[1] = fmaf(av.y, wsg, asg[1]);
        amu[2] = fmaf(av.z, wmu, amu[2]); asg[2] = fmaf(av.z, wsg, asg[2]);
        amu[3] = fmaf(av.w, wmu, amu[3]); asg[3] = fmaf(av.w, wsg, asg[3]);
    }
    const float bmu = b2[col], bsg = b2[col + 256];
#pragma unroll
    for (int j = 0; j < 4; j++) {
        const int s = sbase + sg + j;
        float mu = amu[j] + bmu;
        float sr = asg[j] + bsg;
        float sp = fmaxf(sr, 0.f) + log1pf(expf(-fabsf(sr)));
        out[s * 256 + col] = mu + (sp + 1e-4f) * noise[s * 256 + col];
    }
}

extern "C" void kernel_launch(void* const* d_in, const int* in_sizes, int n_in,
                              void* d_out, int out_size) {
    const float* pos     = (const float*)d_in[0];
    const float* feature = (const float*)d_in[1];
    // d_in[2] = batch: structurally i >> 11, never read
    const float* W1      = (const float*)d_in[3];
    const float* b1      = (const float*)d_in[4];
    const float* W2      = (const float*)d_in[5];
    const float* b2      = (const float*)d_in[6];
    const float* noise   = (const float*)d_in[7];
    float* out = (float*)d_out;

    cudaFuncSetAttribute(pointconv_kernel,
                         cudaFuncAttributeMaxDynamicSharedMemorySize, SMEM_BYTES);

    pointconv_kernel<<<NB, 512, SMEM_BYTES>>>(pos, feature, W1, b1);
    head_kernel<<<dim3(2, 16), 256>>>(W2, b2, noise, out);
}